// round 6
// baseline (speedup 1.0000x reference)
#include <cuda_runtime.h>
#include <cuda_bf16.h>

#define NU 8
#define MA 1024
#define NPAIRS 28              // NU*(NU-1)/2
#define JC 32                  // j chunks per unit
#define JT 32                  // j tile size
#define THREADS 256
#define PAIR_BLOCKS (NPAIRS * 2 * JC)    // 1792 (2 i-halves)
#define TOTAL_BLOCKS (PAIR_BLOCKS + NU)  // +8 L1 blocks

__device__ float g_acc;        // single accumulator; reset by finalizer
__device__ unsigned g_ticket;  // arrival counter; reset by finalizer

__device__ __forceinline__ float ex2f(float x) {
    float r;
    asm("ex2.approx.f32 %0, %1;" : "=r"(*(unsigned*)&r) : "r"(*(unsigned*)&x));
    return r;
}

// Build rotation matrices + positions into shared (threads 0..7, one unit each)
__device__ __forceinline__ void build_R(float (*Rsh)[12],
                                        const float* __restrict__ pos,
                                        const float* __restrict__ euler,
                                        int tid) {
    if (tid < NU) {
        float phi = euler[tid * 3 + 0];
        float the = euler[tid * 3 + 1];
        float psi = euler[tid * 3 + 2];
        float cp = __cosf(phi), sp = __sinf(phi);
        float ct = __cosf(the), st = __sinf(the);
        float cs = __cosf(psi), ss = __sinf(psi);
        // R = Rz(psi) @ Ry(theta) @ Rx(phi)
        Rsh[tid][0] = cs * ct;
        Rsh[tid][1] = -ss * cp + cs * st * sp;
        Rsh[tid][2] = ss * sp + cs * st * cp;
        Rsh[tid][3] = ss * ct;
        Rsh[tid][4] = cs * cp + ss * st * sp;
        Rsh[tid][5] = -cs * sp + ss * st * cp;
        Rsh[tid][6] = -st;
        Rsh[tid][7] = ct * sp;
        Rsh[tid][8] = ct * cp;
        Rsh[tid][9]  = pos[tid * 3 + 0];
        Rsh[tid][10] = pos[tid * 3 + 1];
        Rsh[tid][11] = pos[tid * 3 + 2];
    }
}

// Transform atom m with unit u's rotation+position
__device__ __forceinline__ void xform(const float (*Rsh)[12],
                                      const float* __restrict__ coords,
                                      int u, int m,
                                      float& px, float& py, float& pz, float& sq) {
    float cx = coords[m * 3 + 0];
    float cy = coords[m * 3 + 1];
    float cz = coords[m * 3 + 2];
    const float* R = Rsh[u];
    px = fmaf(R[0], cx, fmaf(R[1], cy, fmaf(R[2], cz, R[9])));
    py = fmaf(R[3], cx, fmaf(R[4], cy, fmaf(R[5], cz, R[10])));
    pz = fmaf(R[6], cx, fmaf(R[7], cy, fmaf(R[8], cz, R[11])));
    sq = px * px + py * py + pz * pz;
}

// ---------------------------------------------------------------------------
// Single fused kernel, 256-thread blocks, fully scalar inner loop.
// Blocks [0, 1792): pair tiles: 512 i (2/thread) x 32 j.
// Blocks [1792, 1800): L1 per unit (+ L_com in the first one).
// pen = exp2(c_i) * exp2(c_j + dot(Pi', Pj')),  P' = S*p, S^2 = 2*log2e,
// c = log2e*(0.5 - |p|^2)   =>  product = exp(1 - d2)
// ---------------------------------------------------------------------------
__global__ void __launch_bounds__(THREADS, 6) fused_kernel(const float* __restrict__ pos,
                                                           const float* __restrict__ euler,
                                                           const float* __restrict__ coords,
                                                           float* __restrict__ out) {
    __shared__ float Rsh[NU][12];
    __shared__ __align__(16) float sj[4][JT];   // SoA j tile: X, Y, Z, c
    __shared__ float wsum[THREADS / 32];

    const float LOG2E = 1.4426950408889634f;
    const float S = 1.6986436005760381f;        // sqrt(2*log2e)
    int tid = threadIdx.x;
    int b = blockIdx.x;

    build_R(Rsh, pos, euler, tid);
    __syncthreads();

    float blockContrib = 0.0f;   // value thread 0 will atomicAdd

    if (b < PAIR_BLOCKS) {
        int p  = b >> 6;
        int ih = (b >> 5) & 1;
        int jc = b & 31;
        // pair index -> (u, v), u < v
        int rem = p, u = 0, row = NU - 1;
        while (rem >= row) { rem -= row; row--; u++; }
        int v = u + 1 + rem;

        // Stage j tile (unit v)
        if (tid < JT) {
            float px, py, pz, sq;
            xform(Rsh, coords, v, jc * JT + tid, px, py, pz, sq);
            sj[0][tid] = S * px;
            sj[1][tid] = S * py;
            sj[2][tid] = S * pz;
            sj[3][tid] = LOG2E * (0.5f - sq);
        }

        // i points (unit u): 2 per thread, scalar pre-scaled
        float px0, py0, pz0, sq0, px1, py1, pz1, sq1;
        xform(Rsh, coords, u, ih * 512 + tid,        px0, py0, pz0, sq0);
        xform(Rsh, coords, u, ih * 512 + tid + 256,  px1, py1, pz1, sq1);
        float dx0 = S * px0, dy0 = S * py0, dz0 = S * pz0;
        float dx1 = S * px1, dy1 = S * py1, dz1 = S * pz1;
        float e0 = ex2f(LOG2E * (0.5f - sq0));
        float e1 = ex2f(LOG2E * (0.5f - sq1));

        __syncthreads();

        const float2* xp = reinterpret_cast<const float2*>(sj[0]);
        const float2* yp = reinterpret_cast<const float2*>(sj[1]);
        const float2* zp = reinterpret_cast<const float2*>(sj[2]);
        const float2* cp = reinterpret_cast<const float2*>(sj[3]);

        // scalar accumulators (e_i applied after the loop)
        float s00 = 0.f, s01 = 0.f, s10 = 0.f, s11 = 0.f;

#pragma unroll
        for (int t = 0; t < JT / 2; t++) {
            float2 xj = xp[t];
            float2 yj = yp[t];
            float2 zj = zp[t];
            float2 cj = cp[t];

            float a0 = fmaf(dx0, xj.x, cj.x);
            a0 = fmaf(dy0, yj.x, a0);
            a0 = fmaf(dz0, zj.x, a0);
            s00 += ex2f(a0);

            float b0 = fmaf(dx0, xj.y, cj.y);
            b0 = fmaf(dy0, yj.y, b0);
            b0 = fmaf(dz0, zj.y, b0);
            s01 += ex2f(b0);

            float a1 = fmaf(dx1, xj.x, cj.x);
            a1 = fmaf(dy1, yj.x, a1);
            a1 = fmaf(dz1, zj.x, a1);
            s10 += ex2f(a1);

            float b1 = fmaf(dx1, xj.y, cj.y);
            b1 = fmaf(dy1, yj.y, b1);
            b1 = fmaf(dz1, zj.y, b1);
            s11 += ex2f(b1);
        }

        float s = fmaf(e0, s00 + s01, e1 * (s10 + s11));
#pragma unroll
        for (int o = 16; o > 0; o >>= 1)
            s += __shfl_xor_sync(0xFFFFFFFFu, s, o);
        if ((tid & 31) == 0) wsum[tid >> 5] = s;
        __syncthreads();
        if (tid == 0) {
            float bs = 0.f;
#pragma unroll
            for (int w = 0; w < THREADS / 32; w++) bs += wsum[w];
            blockContrib = 0.5f * bs;      // LAMBDA1 = 0.5
        }
    } else {
        // L1 block for unit u (+ L_com in the u==0 block)
        int u = b - PAIR_BLOCKS;
        float l1 = 0.0f;
#pragma unroll
        for (int k = 0; k < MA / THREADS; k++) {
            float px, py, pz, sq;
            xform(Rsh, coords, u, k * THREADS + tid, px, py, pz, sq);
            l1 += sq;
        }
#pragma unroll
        for (int o = 16; o > 0; o >>= 1)
            l1 += __shfl_xor_sync(0xFFFFFFFFu, l1, o);
        if ((tid & 31) == 0) wsum[tid >> 5] = l1;
        __syncthreads();
        if (tid == 0) {
            float bs = 0.f;
#pragma unroll
            for (int w = 0; w < THREADS / 32; w++) bs += wsum[w];
            blockContrib = bs / (float)NU;      // contribution to L1 mean
            if (u == 0) {
                float ccx = 0.f, ccy = 0.f, ccz = 0.f;
#pragma unroll
                for (int uu = 0; uu < NU; uu++) {
                    ccx += Rsh[uu][9]; ccy += Rsh[uu][10]; ccz += Rsh[uu][11];
                }
                blockContrib += ccx * ccx + ccy * ccy + ccz * ccz;   // ALPHA = 1
            }
        }
    }

    // Accumulate + ticket finalize (thread 0 of every block)
    if (tid == 0) {
        atomicAdd(&g_acc, blockContrib);
        __threadfence();
        unsigned old = atomicAdd(&g_ticket, 1u);
        if (old == TOTAL_BLOCKS - 1) {
            __threadfence();
            float total = *((volatile float*)&g_acc);
            out[0] = total;
            g_acc = 0.0f;        // reset for next graph replay
            g_ticket = 0u;
        }
    }
}

extern "C" void kernel_launch(void* const* d_in, const int* in_sizes, int n_in,
                              void* d_out, int out_size) {
    const float* positions = (const float*)d_in[0];
    const float* euler     = (const float*)d_in[1];
    const float* coords    = (const float*)d_in[2];
    float* out = (float*)d_out;

    fused_kernel<<<TOTAL_BLOCKS, THREADS>>>(positions, euler, coords, out);
}

// round 7
// speedup vs baseline: 1.0609x; 1.0609x over previous
#include <cuda_runtime.h>
#include <cuda_bf16.h>

#define NU 8
#define MA 1024
#define NPAIRS 28              // NU*(NU-1)/2
#define JC 32                  // j chunks per unit
#define JT 32                  // j tile size
#define THREADS 512
#define PAIR_BLOCKS (NPAIRS * JC)        // 896 (full 1024 i per block)
#define TOTAL_BLOCKS (PAIR_BLOCKS + NU)  // +8 L1 blocks

__device__ float g_acc;        // single accumulator; reset by finalizer
__device__ unsigned g_ticket;  // arrival counter; reset by finalizer

__device__ __forceinline__ unsigned long long pk2(float a, float b) {
    unsigned long long r;
    asm("mov.b64 %0, {%1, %2};" : "=l"(r) : "f"(a), "f"(b));
    return r;
}
__device__ __forceinline__ void upk2(float& a, float& b, unsigned long long v) {
    asm("mov.b64 {%0, %1}, %2;" : "=f"(a), "=f"(b) : "l"(v));
}
__device__ __forceinline__ unsigned long long fma2(unsigned long long a, unsigned long long b, unsigned long long c) {
    unsigned long long d;
    asm("fma.rn.f32x2 %0, %1, %2, %3;" : "=l"(d) : "l"(a), "l"(b), "l"(c));
    return d;
}
__device__ __forceinline__ float ex2f(float x) {
    float r;
    asm("ex2.approx.f32 %0, %1;" : "=r"(*(unsigned*)&r) : "r"(*(unsigned*)&x));
    return r;
}

// Build rotation matrices + positions into shared (threads 0..7, one unit each)
__device__ __forceinline__ void build_R(float (*Rsh)[12],
                                        const float* __restrict__ pos,
                                        const float* __restrict__ euler,
                                        int tid) {
    if (tid < NU) {
        float phi = euler[tid * 3 + 0];
        float the = euler[tid * 3 + 1];
        float psi = euler[tid * 3 + 2];
        float cp = __cosf(phi), sp = __sinf(phi);
        float ct = __cosf(the), st = __sinf(the);
        float cs = __cosf(psi), ss = __sinf(psi);
        // R = Rz(psi) @ Ry(theta) @ Rx(phi)
        Rsh[tid][0] = cs * ct;
        Rsh[tid][1] = -ss * cp + cs * st * sp;
        Rsh[tid][2] = ss * sp + cs * st * cp;
        Rsh[tid][3] = ss * ct;
        Rsh[tid][4] = cs * cp + ss * st * sp;
        Rsh[tid][5] = -cs * sp + ss * st * cp;
        Rsh[tid][6] = -st;
        Rsh[tid][7] = ct * sp;
        Rsh[tid][8] = ct * cp;
        Rsh[tid][9]  = pos[tid * 3 + 0];
        Rsh[tid][10] = pos[tid * 3 + 1];
        Rsh[tid][11] = pos[tid * 3 + 2];
    }
}

// Transform atom m with unit u's rotation+position
__device__ __forceinline__ void xform(const float (*Rsh)[12],
                                      const float* __restrict__ coords,
                                      int u, int m,
                                      float& px, float& py, float& pz, float& sq) {
    float cx = coords[m * 3 + 0];
    float cy = coords[m * 3 + 1];
    float cz = coords[m * 3 + 2];
    const float* R = Rsh[u];
    px = fmaf(R[0], cx, fmaf(R[1], cy, fmaf(R[2], cz, R[9])));
    py = fmaf(R[3], cx, fmaf(R[4], cy, fmaf(R[5], cz, R[10])));
    pz = fmaf(R[6], cx, fmaf(R[7], cy, fmaf(R[8], cz, R[11])));
    sq = px * px + py * py + pz * pz;
}

// ---------------------------------------------------------------------------
// Single fused kernel, 512-thread blocks.
// Blocks [0, 896): pair tiles: full 1024 i (2/thread) x 32 j.
// Blocks [896, 904): L1 per unit (+ L_com in the first one).
// pen = exp2(c_i) * exp2(c_j + dot(Pi', Pj')),  P' = S*p, S^2 = 2*log2e,
// c = log2e*(0.5 - |p|^2)   =>  product = exp(1 - d2)
// Inner loop: f32x2 fma for the dot, scalar EX2 + scalar FADD accumulate.
// ---------------------------------------------------------------------------
__global__ void __launch_bounds__(THREADS) fused_kernel(const float* __restrict__ pos,
                                                        const float* __restrict__ euler,
                                                        const float* __restrict__ coords,
                                                        float* __restrict__ out) {
    __shared__ float Rsh[NU][12];
    __shared__ __align__(16) float sj[4][JT];   // SoA j tile: X, Y, Z, c
    __shared__ float wsum[THREADS / 32];

    const float LOG2E = 1.4426950408889634f;
    const float S = 1.6986436005760381f;        // sqrt(2*log2e)
    int tid = threadIdx.x;
    int b = blockIdx.x;

    build_R(Rsh, pos, euler, tid);
    __syncthreads();

    float blockContrib = 0.0f;   // value thread 0 will atomicAdd

    if (b < PAIR_BLOCKS) {
        int p  = b >> 5;          // pair index
        int jc = b & 31;          // j chunk
        // pair index -> (u, v), u < v
        int rem = p, u = 0, row = NU - 1;
        while (rem >= row) { rem -= row; row--; u++; }
        int v = u + 1 + rem;

        // Stage j tile (unit v)
        if (tid < JT) {
            float px, py, pz, sq;
            xform(Rsh, coords, v, jc * JT + tid, px, py, pz, sq);
            sj[0][tid] = S * px;
            sj[1][tid] = S * py;
            sj[2][tid] = S * pz;
            sj[3][tid] = LOG2E * (0.5f - sq);
        }

        // i points (unit u): 2 per thread
        float px0, py0, pz0, sq0, px1, py1, pz1, sq1;
        xform(Rsh, coords, u, tid,           px0, py0, pz0, sq0);
        xform(Rsh, coords, u, tid + THREADS, px1, py1, pz1, sq1);

        unsigned long long DX0 = pk2(S * px0, S * px0), DY0 = pk2(S * py0, S * py0), DZ0 = pk2(S * pz0, S * pz0);
        unsigned long long DX1 = pk2(S * px1, S * px1), DY1 = pk2(S * py1, S * py1), DZ1 = pk2(S * pz1, S * pz1);
        float e0 = ex2f(LOG2E * (0.5f - sq0));
        float e1 = ex2f(LOG2E * (0.5f - sq1));

        __syncthreads();

        const unsigned long long* xp = reinterpret_cast<const unsigned long long*>(sj[0]);
        const unsigned long long* yp = reinterpret_cast<const unsigned long long*>(sj[1]);
        const unsigned long long* zp = reinterpret_cast<const unsigned long long*>(sj[2]);
        const unsigned long long* cp = reinterpret_cast<const unsigned long long*>(sj[3]);

        float s0a = 0.f, s0b = 0.f, s1a = 0.f, s1b = 0.f;

#pragma unroll
        for (int t = 0; t < JT / 2; t++) {
            unsigned long long XJ = xp[t];
            unsigned long long YJ = yp[t];
            unsigned long long ZJ = zp[t];
            unsigned long long CJ = cp[t];
            float lo, hi;

            unsigned long long t0 = fma2(DX0, XJ, CJ);
            t0 = fma2(DY0, YJ, t0);
            t0 = fma2(DZ0, ZJ, t0);
            upk2(lo, hi, t0);
            s0a += ex2f(lo);
            s0b += ex2f(hi);

            unsigned long long t1 = fma2(DX1, XJ, CJ);
            t1 = fma2(DY1, YJ, t1);
            t1 = fma2(DZ1, ZJ, t1);
            upk2(lo, hi, t1);
            s1a += ex2f(lo);
            s1b += ex2f(hi);
        }

        float s = fmaf(e0, s0a + s0b, e1 * (s1a + s1b));
#pragma unroll
        for (int o = 16; o > 0; o >>= 1)
            s += __shfl_xor_sync(0xFFFFFFFFu, s, o);
        if ((tid & 31) == 0) wsum[tid >> 5] = s;
        __syncthreads();
        if (tid == 0) {
            float bs = 0.f;
#pragma unroll
            for (int w = 0; w < THREADS / 32; w++) bs += wsum[w];
            blockContrib = 0.5f * bs;      // LAMBDA1 = 0.5
        }
    } else {
        // L1 block for unit u (+ L_com in the u==0 block)
        int u = b - PAIR_BLOCKS;
        float l1 = 0.0f;
#pragma unroll
        for (int k = 0; k < MA / THREADS; k++) {
            float px, py, pz, sq;
            xform(Rsh, coords, u, k * THREADS + tid, px, py, pz, sq);
            l1 += sq;
        }
#pragma unroll
        for (int o = 16; o > 0; o >>= 1)
            l1 += __shfl_xor_sync(0xFFFFFFFFu, l1, o);
        if ((tid & 31) == 0) wsum[tid >> 5] = l1;
        __syncthreads();
        if (tid == 0) {
            float bs = 0.f;
#pragma unroll
            for (int w = 0; w < THREADS / 32; w++) bs += wsum[w];
            blockContrib = bs / (float)NU;      // contribution to L1 mean
            if (u == 0) {
                float ccx = 0.f, ccy = 0.f, ccz = 0.f;
#pragma unroll
                for (int uu = 0; uu < NU; uu++) {
                    ccx += Rsh[uu][9]; ccy += Rsh[uu][10]; ccz += Rsh[uu][11];
                }
                blockContrib += ccx * ccx + ccy * ccy + ccz * ccz;   // ALPHA = 1
            }
        }
    }

    // Accumulate + ticket finalize (thread 0 of every block)
    if (tid == 0) {
        atomicAdd(&g_acc, blockContrib);
        __threadfence();
        unsigned old = atomicAdd(&g_ticket, 1u);
        if (old == TOTAL_BLOCKS - 1) {
            __threadfence();
            float total = *((volatile float*)&g_acc);
            out[0] = total;
            g_acc = 0.0f;        // reset for next graph replay
            g_ticket = 0u;
        }
    }
}

extern "C" void kernel_launch(void* const* d_in, const int* in_sizes, int n_in,
                              void* d_out, int out_size) {
    const float* positions = (const float*)d_in[0];
    const float* euler     = (const float*)d_in[1];
    const float* coords    = (const float*)d_in[2];
    float* out = (float*)d_out;

    fused_kernel<<<TOTAL_BLOCKS, THREADS>>>(positions, euler, coords, out);
}

// round 8
// speedup vs baseline: 1.1045x; 1.0410x over previous
#include <cuda_runtime.h>
#include <cuda_bf16.h>

#define NU 8
#define MA 1024
#define NPTS (NU * MA)
#define NPAIRS 28              // NU*(NU-1)/2
#define JC 32                  // j chunks per unit
#define JT 32                  // j tile size
#define THREADS 256
#define PREP_BLOCKS 32
#define PAIR_BLOCKS (NPAIRS * JC)                 // 896 (full 1024 i per block, IPT=4)
#define TOTAL_BLOCKS (PREP_BLOCKS + PAIR_BLOCKS)  // 928

__device__ float4 g_pts[NPTS];   // (X, Y, Z, c): X = S*px, c = log2e*(0.5-|p|^2)
__device__ float g_acc;          // single accumulator; reset by finalizer
__device__ unsigned g_ticket;    // all-block arrival counter; reset by finalizer
__device__ unsigned g_prep;      // prep-block arrival counter; reset by finalizer
__device__ volatile unsigned g_flag;  // release flag; reset by finalizer

__device__ __forceinline__ unsigned long long pk2(float a, float b) {
    unsigned long long r;
    asm("mov.b64 %0, {%1, %2};" : "=l"(r) : "f"(a), "f"(b));
    return r;
}
__device__ __forceinline__ void upk2(float& a, float& b, unsigned long long v) {
    asm("mov.b64 {%0, %1}, %2;" : "=f"(a), "=f"(b) : "l"(v));
}
__device__ __forceinline__ unsigned long long fma2(unsigned long long a, unsigned long long b, unsigned long long c) {
    unsigned long long d;
    asm("fma.rn.f32x2 %0, %1, %2, %3;" : "=l"(d) : "l"(a), "l"(b), "l"(c));
    return d;
}
__device__ __forceinline__ float ex2f(float x) {
    float r;
    asm("ex2.approx.f32 %0, %1;" : "=r"(*(unsigned*)&r) : "r"(*(unsigned*)&x));
    return r;
}

// ---------------------------------------------------------------------------
// Single fused kernel, producer/consumer split:
//  blocks [0,32):   prep — transform 256 points each into g_pts, L1/L_com
//                   partials into g_acc, then release g_flag.
//  blocks [32,928): pair tiles — spin on g_flag, then 1024 i (4/thread) x 32 j.
// pen = exp2(c_i) * exp2(c_j + dot(Pi', Pj')),  P' = S*p, S^2 = 2*log2e,
// c = log2e*(0.5 - |p|^2)  =>  product = exp(1 - d2)
// ---------------------------------------------------------------------------
__global__ void __launch_bounds__(THREADS) fused_kernel(const float* __restrict__ pos,
                                                        const float* __restrict__ euler,
                                                        const float* __restrict__ coords,
                                                        float* __restrict__ out) {
    __shared__ float wsum[THREADS / 32];
    const float LOG2E = 1.4426950408889634f;
    const float S = 1.6986436005760381f;        // sqrt(2*log2e)
    int tid = threadIdx.x;
    int b = blockIdx.x;

    float blockContrib = 0.0f;

    if (b < PREP_BLOCKS) {
        // ---------------- prep role ----------------
        __shared__ float Rsh[NU][12];
        if (tid < NU) {
            float phi = euler[tid * 3 + 0];
            float the = euler[tid * 3 + 1];
            float psi = euler[tid * 3 + 2];
            float cp = __cosf(phi), sp = __sinf(phi);
            float ct = __cosf(the), st = __sinf(the);
            float cs = __cosf(psi), ss = __sinf(psi);
            Rsh[tid][0] = cs * ct;
            Rsh[tid][1] = -ss * cp + cs * st * sp;
            Rsh[tid][2] = ss * sp + cs * st * cp;
            Rsh[tid][3] = ss * ct;
            Rsh[tid][4] = cs * cp + ss * st * sp;
            Rsh[tid][5] = -cs * sp + ss * st * cp;
            Rsh[tid][6] = -st;
            Rsh[tid][7] = ct * sp;
            Rsh[tid][8] = ct * cp;
            Rsh[tid][9]  = pos[tid * 3 + 0];
            Rsh[tid][10] = pos[tid * 3 + 1];
            Rsh[tid][11] = pos[tid * 3 + 2];
        }
        __syncthreads();

        int idx = b * THREADS + tid;
        int u = idx >> 10;
        int m = idx & (MA - 1);
        float cx = coords[m * 3 + 0];
        float cy = coords[m * 3 + 1];
        float cz = coords[m * 3 + 2];
        const float* R = Rsh[u];
        float px = fmaf(R[0], cx, fmaf(R[1], cy, fmaf(R[2], cz, R[9])));
        float py = fmaf(R[3], cx, fmaf(R[4], cy, fmaf(R[5], cz, R[10])));
        float pz = fmaf(R[6], cx, fmaf(R[7], cy, fmaf(R[8], cz, R[11])));
        float sq = px * px + py * py + pz * pz;
        float4 o;
        o.x = S * px;
        o.y = S * py;
        o.z = S * pz;
        o.w = LOG2E * (0.5f - sq);
        g_pts[idx] = o;

        // reduce sq for L1
        float l1 = sq;
#pragma unroll
        for (int off = 16; off > 0; off >>= 1)
            l1 += __shfl_xor_sync(0xFFFFFFFFu, l1, off);
        if ((tid & 31) == 0) wsum[tid >> 5] = l1;
        __syncthreads();
        if (tid == 0) {
            float bs = 0.f;
#pragma unroll
            for (int w = 0; w < THREADS / 32; w++) bs += wsum[w];
            blockContrib = bs / (float)NU;          // L1 mean partial
            if (b == 0) {
                float ccx = 0.f, ccy = 0.f, ccz = 0.f;
#pragma unroll
                for (int uu = 0; uu < NU; uu++) {
                    ccx += Rsh[uu][9]; ccy += Rsh[uu][10]; ccz += Rsh[uu][11];
                }
                blockContrib += ccx * ccx + ccy * ccy + ccz * ccz;   // ALPHA = 1
            }
            // release protocol: data out, fence, count, last sets flag
            __threadfence();
            unsigned oldp = atomicAdd(&g_prep, 1u);
            if (oldp == PREP_BLOCKS - 1) {
                g_flag = 1u;        // volatile store, after fence
            }
        }
    } else {
        // ---------------- pair role ----------------
        // paired SoA j tile: [t][0..1]=x pair, [t][2..3]=y pair / z,c
        __shared__ __align__(16) float sjXY[JT / 2][4];
        __shared__ __align__(16) float sjZC[JT / 2][4];

        int pb = b - PREP_BLOCKS;
        int p  = pb >> 5;         // pair index
        int jc = pb & 31;         // j chunk
        int rem = p, u = 0, row = NU - 1;
        while (rem >= row) { rem -= row; row--; u++; }
        int v = u + 1 + rem;

        // wait for prep release
        if (tid == 0) {
            while (g_flag == 0u) { }
            __threadfence();      // acquire: order g_pts reads after flag
        }
        __syncthreads();

        // stage j tile
        if (tid < JT) {
            float4 q = g_pts[v * MA + jc * JT + tid];
            int t = tid >> 1, h = tid & 1;
            sjXY[t][h]     = q.x;
            sjXY[t][2 + h] = q.y;
            sjZC[t][h]     = q.z;
            sjZC[t][2 + h] = q.w;
        }

        // 4 i points per thread (coalesced LDG.128)
        int ibase = u * MA + tid;
        float4 a0 = g_pts[ibase];
        float4 a1 = g_pts[ibase + THREADS];
        float4 a2 = g_pts[ibase + 2 * THREADS];
        float4 a3 = g_pts[ibase + 3 * THREADS];

        unsigned long long DX0 = pk2(a0.x, a0.x), DY0 = pk2(a0.y, a0.y), DZ0 = pk2(a0.z, a0.z);
        unsigned long long DX1 = pk2(a1.x, a1.x), DY1 = pk2(a1.y, a1.y), DZ1 = pk2(a1.z, a1.z);
        unsigned long long DX2 = pk2(a2.x, a2.x), DY2 = pk2(a2.y, a2.y), DZ2 = pk2(a2.z, a2.z);
        unsigned long long DX3 = pk2(a3.x, a3.x), DY3 = pk2(a3.y, a3.y), DZ3 = pk2(a3.z, a3.z);
        float e0 = ex2f(a0.w), e1 = ex2f(a1.w), e2 = ex2f(a2.w), e3 = ex2f(a3.w);

        __syncthreads();

        const ulonglong2* xyp = reinterpret_cast<const ulonglong2*>(sjXY);
        const ulonglong2* zcp = reinterpret_cast<const ulonglong2*>(sjZC);

        float s0 = 0.f, s1 = 0.f, s2 = 0.f, s3 = 0.f;

#pragma unroll
        for (int t = 0; t < JT / 2; t++) {
            ulonglong2 xy = xyp[t];
            ulonglong2 zc = zcp[t];
            unsigned long long XJ = xy.x, YJ = xy.y, ZJ = zc.x, CJ = zc.y;
            float lo, hi;

            unsigned long long t0 = fma2(DX0, XJ, CJ);
            t0 = fma2(DY0, YJ, t0);
            t0 = fma2(DZ0, ZJ, t0);
            upk2(lo, hi, t0);
            s0 += ex2f(lo);
            s0 += ex2f(hi);

            unsigned long long t1 = fma2(DX1, XJ, CJ);
            t1 = fma2(DY1, YJ, t1);
            t1 = fma2(DZ1, ZJ, t1);
            upk2(lo, hi, t1);
            s1 += ex2f(lo);
            s1 += ex2f(hi);

            unsigned long long t2 = fma2(DX2, XJ, CJ);
            t2 = fma2(DY2, YJ, t2);
            t2 = fma2(DZ2, ZJ, t2);
            upk2(lo, hi, t2);
            s2 += ex2f(lo);
            s2 += ex2f(hi);

            unsigned long long t3 = fma2(DX3, XJ, CJ);
            t3 = fma2(DY3, YJ, t3);
            t3 = fma2(DZ3, ZJ, t3);
            upk2(lo, hi, t3);
            s3 += ex2f(lo);
            s3 += ex2f(hi);
        }

        float s = fmaf(e0, s0, fmaf(e1, s1, fmaf(e2, s2, e3 * s3)));
#pragma unroll
        for (int o = 16; o > 0; o >>= 1)
            s += __shfl_xor_sync(0xFFFFFFFFu, s, o);
        if ((tid & 31) == 0) wsum[tid >> 5] = s;
        __syncthreads();
        if (tid == 0) {
            float bs = 0.f;
#pragma unroll
            for (int w = 0; w < THREADS / 32; w++) bs += wsum[w];
            blockContrib = 0.5f * bs;      // LAMBDA1 = 0.5
        }
    }

    // Accumulate + ticket finalize (thread 0 of every block)
    if (tid == 0) {
        atomicAdd(&g_acc, blockContrib);
        __threadfence();
        unsigned old = atomicAdd(&g_ticket, 1u);
        if (old == TOTAL_BLOCKS - 1) {
            __threadfence();
            float total = *((volatile float*)&g_acc);
            out[0] = total;
            g_acc = 0.0f;        // reset for next graph replay
            g_ticket = 0u;
            g_prep = 0u;
            g_flag = 0u;
        }
    }
}

extern "C" void kernel_launch(void* const* d_in, const int* in_sizes, int n_in,
                              void* d_out, int out_size) {
    const float* positions = (const float*)d_in[0];
    const float* euler     = (const float*)d_in[1];
    const float* coords    = (const float*)d_in[2];
    float* out = (float*)d_out;

    fused_kernel<<<TOTAL_BLOCKS, THREADS>>>(positions, euler, coords, out);
}